// round 11
// baseline (speedup 1.0000x reference)
#include <cuda_runtime.h>
#include <cuda_bf16.h>
#include <cstddef>

// x[64,512,128] @ Wx[128,1024] + b -> XP (in d_out); then
// h_t = tanh(xp_t + h_{t-1} @ Wh[1024,1024]); out[b,t,:] = h_t.
#define BB 64
#define TT 512
#define DD 128
#define HH 1024

typedef unsigned long long ull;

__device__ __forceinline__ ull pk2(float lo, float hi) {
    ull r; asm("mov.b64 %0, {%1, %2};" : "=l"(r) : "f"(lo), "f"(hi)); return r;
}
__device__ __forceinline__ float2 upk2(ull v) {
    float lo, hi; asm("mov.b64 {%0, %1}, %2;" : "=f"(lo), "=f"(hi) : "l"(v));
    return make_float2(lo, hi);
}
__device__ __forceinline__ ull ffma2(ull a, ull b, ull c) {
    ull d; asm("fma.rn.f32x2 %0, %1, %2, %3;" : "=l"(d) : "l"(a), "l"(b), "l"(c));
    return d;
}
__device__ __forceinline__ int ld_acq(const int* p) {
    int v; asm volatile("ld.acquire.gpu.global.s32 %0, [%1];" : "=r"(v) : "l"(p));
    return v;
}
__device__ __forceinline__ void red_rel_add1(int* p) {
    asm volatile("red.release.gpu.global.add.s32 [%0], 1;" :: "l"(p) : "memory");
}
// fast tanh: exp-based, ~1e-6 rel err; clamp avoids inf/inf.
__device__ __forceinline__ float fast_tanh(float x) {
    x = fminf(fmaxf(x, -15.f), 15.f);
    float e = __expf(x + x);
    return __fdividef(e - 1.f, e + 1.f);
}

// ---------- global scratch ----------
__device__ float g_h[2][BB][HH];         // h double buffer, row-major [b][k]
__device__ int   g_flags[4][TT][8];      // (group, step, k-chunk) warp arrivals

// =====================================================================
// Kernel 1: XP = x @ Wx + b  -> d_out   (M=32768, K=128, N=1024)
// Block (0,0) also resets the step flags.
// =====================================================================
__global__ __launch_bounds__(256) void xp_gemm(
    const float* __restrict__ x, const float* __restrict__ Wx,
    const float* __restrict__ bias, float* __restrict__ out)
{
    __shared__ float xs[64 * 68];
    __shared__ float ws[64 * 64];

    const int tid = threadIdx.x;
    if (blockIdx.x == 0 && blockIdx.y == 0) {
        int* f = &g_flags[0][0][0];
        #pragma unroll
        for (int i = tid; i < 4 * TT * 8; i += 256) f[i] = 0;
    }

    const int m0 = blockIdx.x * 64;
    const int n0 = blockIdx.y * 64;
    const int ty = tid >> 4;
    const int tx = tid & 15;

    ull acc01[4] = {0ull, 0ull, 0ull, 0ull};
    ull acc23[4] = {0ull, 0ull, 0ull, 0ull};

    for (int k0 = 0; k0 < DD; k0 += 64) {
        __syncthreads();
        #pragma unroll
        for (int i = tid; i < 1024; i += 256) {
            int r = i >> 4, q = i & 15;
            ((float4*)xs)[r * 17 + q] =
                *(const float4*)&x[(size_t)(m0 + r) * DD + k0 + 4 * q];
        }
        #pragma unroll
        for (int i = tid; i < 1024; i += 256) {
            int r = i >> 4, q = i & 15;
            ((float4*)ws)[i] =
                *(const float4*)&Wx[(size_t)(k0 + r) * HH + n0 + 4 * q];
        }
        __syncthreads();

        #pragma unroll 8
        for (int kk = 0; kk < 64; kk++) {
            ulonglong2 wv = *(const ulonglong2*)&ws[kk * 64 + 4 * tx];
            #pragma unroll
            for (int i = 0; i < 4; i++) {
                float a = xs[(4 * ty + i) * 68 + kk];
                ull aa = pk2(a, a);
                acc01[i] = ffma2(aa, wv.x, acc01[i]);
                acc23[i] = ffma2(aa, wv.y, acc23[i]);
            }
        }
    }

    float4 bv = *(const float4*)&bias[n0 + 4 * tx];
    #pragma unroll
    for (int i = 0; i < 4; i++) {
        float2 p0 = upk2(acc01[i]);
        float2 p1 = upk2(acc23[i]);
        float4 r;
        r.x = p0.x + bv.x; r.y = p0.y + bv.y;
        r.z = p1.x + bv.z; r.w = p1.y + bv.w;
        *(float4*)&out[(size_t)(m0 + 4 * ty + i) * HH + n0 + 4 * tx] = r;
    }
}

// =====================================================================
// Kernel 2: persistent recurrence, TWO independent chains per SM.
// 128 CTAs x 512 threads. CTA cid: col slice j = cid&63 (16 cols, Wh
// slice shared by halves); half 0 (warps 0-7): group cid>>6, half 1
// (warps 8-15): group cid>>6 + 2. Halves never sync with each other.
// Per half: warp ks stages+consumes k-chunk ks (128 k x 16 b, 8KB).
// h slot layout: hb[k4][perm(b)], perm(b)=(b&3)*4+(b>>2) — STATIC
// (no per-iter swizzle math). Staging lanes are batch-major so the
// STS pattern is conflict-free (2 wavefronts); LDGs are 16-sector
// (L2-resident h, acceptable). Compute loads: 4 distinct granules
// within 128B -> conflict-free broadcast.
// red[half][parity][8][16][16]; ONE bar.sync(half+1,256) per step;
// parity covers the <=1-step run-ahead the barrier permits.
// Flags target 64 = 8 producer slices x 8 epi warps.
// =====================================================================
#define WB_F4   4096                      /* Wh [256 k4][16 slots] = 64KB */
#define HB_F4   4096                      /* h per half [256 k4][16] = 64KB */
#define RED_ROW 16
#define RED_PAR (8 * 16 * RED_ROW)        /* 2048 floats */
#define SMEM_BYTES (WB_F4*16 + 2*HB_F4*16 + 4*RED_PAR*4)  /* 229,376 B */

__global__ __launch_bounds__(512, 1) void rnn_persist(
    float* __restrict__ out, const float* __restrict__ Wh)
{
    extern __shared__ float4 sm4[];
    float4* wb4  = sm4;                       // [256][16]
    float4* hbb  = sm4 + WB_F4;               // [2][256][16]
    float*  redb = (float*)(sm4 + WB_F4 + 2 * HB_F4); // [2][2][RED_PAR]

    const int tid  = threadIdx.x;
    const int half = tid >> 8;
    const int tid2 = tid & 255;
    const int j    = blockIdx.x & 63;
    const int g    = (blockIdx.x >> 6) + 2 * half;
    const int B0   = 16 * g;
    const int C0   = 16 * j;
    const int jc   = j >> 3;                  // chunk this slice feeds

    // one-time: Wh slice [1024 k][16 c] K-transposed into float4 blocks;
    // col c at slot (c&1)*8 + (c>>1)  (even cols 0-7, odd cols 8-15).
    for (int idx = tid; idx < WB_F4; idx += 512) {
        int k4 = idx >> 4, c = idx & 15;
        const float* p = &Wh[(size_t)(4 * k4) * HH + C0 + c];
        float4 v;
        v.x = p[0]; v.y = p[HH]; v.z = p[2 * HH]; v.w = p[3 * HH];
        wb4[k4 * 16 + ((c & 1) * 8 + (c >> 1))] = v;
    }
    __syncthreads();   // only CTA-wide sync; halves independent after this

    const int ks   = (tid2 >> 5);   // local warp 0..7 = its k-chunk
    const int lane = tid & 31;
    const int cq   = lane & 7;      // cols 2cq, 2cq+1
    const int bq   = lane >> 3;     // batches 4bq..4bq+3

    // staging mapping: batch-major lanes -> static conflict-free STS
    const int sb   = lane & 15;                      // batch
    const int kh   = lane >> 4;                      // k4 parity within pair
    const int sperm = (sb & 3) * 4 + (sb >> 2);      // perm(b)

    const int eb = tid2 >> 4;       // epilogue batch 0..15
    const int ec = tid2 & 15;       // epilogue col 0..15

    float4* hb   = hbb + half * HB_F4;
    float*  redh = redb + half * (2 * RED_PAR);

    for (int t = 0; t < TT; t++) {
        const int p = t & 1;
        float* red = redh + p * RED_PAR;

        // prefetch xp (this thread's own output element)
        size_t ob = ((size_t)(B0 + eb) * TT + t) * HH + C0 + ec;
        float xp = __ldcg(&out[ob]);

        if (t > 0) {
            // wait for this chunk's 8 producer slices (64 warp-arrivals)
            const int* fl = &g_flags[g][t - 1][ks];
            while (ld_acq(fl) < 64) { }

            // stage this warp's 128-k chunk of h_{t-1}:
            // lane = (batch sb, k-half kh); 16 iters of (LDG.128 + STS.128)
            {
                const float4* src = (const float4*)&g_h[p ^ 1][B0 + sb][0];
                const int k4base = 32 * ks + kh;
                #pragma unroll
                for (int i = 0; i < 16; i++) {
                    int k4 = k4base + 2 * i;
                    float4 v = __ldcg(src + k4);
                    hb[k4 * 16 + sperm] = v;
                }
            }
            __syncwarp();

            // compute 32 k4: static slot offsets, 6 LDS.128 + 16 ffma2/iter
            const float4* hrow = hb + (32 * ks) * 16 + bq;   // + 4i at use
            const float4* wp   = wb4 + (32 * ks) * 16;
            ull a[4][2];
            #pragma unroll
            for (int bi = 0; bi < 4; bi++) { a[bi][0] = 0ull; a[bi][1] = 0ull; }

            #pragma unroll 4
            for (int m = 0; m < 32; m++) {
                ulonglong2 w0 = *(const ulonglong2*)(wp + m * 16 + cq);
                ulonglong2 w1 = *(const ulonglong2*)(wp + m * 16 + 8 + cq);
                ulonglong2 h0 = *(const ulonglong2*)(hrow + m * 16 + 0);
                ulonglong2 h1 = *(const ulonglong2*)(hrow + m * 16 + 4);
                ulonglong2 h2 = *(const ulonglong2*)(hrow + m * 16 + 8);
                ulonglong2 h3 = *(const ulonglong2*)(hrow + m * 16 + 12);
                a[0][0] = ffma2(h0.x, w0.x, a[0][0]);
                a[0][0] = ffma2(h0.y, w0.y, a[0][0]);
                a[0][1] = ffma2(h0.x, w1.x, a[0][1]);
                a[0][1] = ffma2(h0.y, w1.y, a[0][1]);
                a[1][0] = ffma2(h1.x, w0.x, a[1][0]);
                a[1][0] = ffma2(h1.y, w0.y, a[1][0]);
                a[1][1] = ffma2(h1.x, w1.x, a[1][1]);
                a[1][1] = ffma2(h1.y, w1.y, a[1][1]);
                a[2][0] = ffma2(h2.x, w0.x, a[2][0]);
                a[2][0] = ffma2(h2.y, w0.y, a[2][0]);
                a[2][1] = ffma2(h2.x, w1.x, a[2][1]);
                a[2][1] = ffma2(h2.y, w1.y, a[2][1]);
                a[3][0] = ffma2(h3.x, w0.x, a[3][0]);
                a[3][0] = ffma2(h3.y, w0.y, a[3][0]);
                a[3][1] = ffma2(h3.x, w1.x, a[3][1]);
                a[3][1] = ffma2(h3.y, w1.y, a[3][1]);
            }
            // NOTE: accumulator index a[bi][*] corresponds to batch with
            // perm slot 4*?+bq... slots hrow+0/4/8/12 + bq hold batches
            // perm^{-1}(4i+bq). perm(b)=(b&3)*4+(b>>2) => slot s=4i+bq
            // has b = (s>>2) + 4*(s&3) = i + 4*bq. So a[i][*] is batch
            // i + 4*bq  (quad-transposed vs R10; red write uses this).

            // horizontal add -> red[ks][b][c]
            #pragma unroll
            for (int bi = 0; bi < 4; bi++) {
                float2 v0 = upk2(a[bi][0]);
                float2 v1 = upk2(a[bi][1]);
                int b = bi + 4 * bq;     // de-permuted batch index
                *(float2*)&red[(ks * 16 + b) * RED_ROW + 2 * cq] =
                    make_float2(v0.x + v0.y, v1.x + v1.y);
            }
        }
        // join this half's 8 warps (drains STS)
        asm volatile("bar.sync %0, 256;" :: "r"(half + 1) : "memory");

        // epilogue: reduce 8 k-chunks, add xp, tanh, publish
        float s = xp;
        if (t > 0) {
            #pragma unroll
            for (int q = 0; q < 8; q++)
                s += red[(q * 16 + eb) * RED_ROW + ec];
        }
        float r = fast_tanh(s);
        g_h[p][B0 + eb][C0 + ec] = r;
        __syncwarp();
        if (lane == 0) red_rel_add1(&g_flags[g][t][jc]);
        out[ob] = r;     // off critical path
    }
}

// =====================================================================
// Launch
// =====================================================================
extern "C" void kernel_launch(void* const* d_in, const int* in_sizes, int n_in,
                              void* d_out, int out_size)
{
    const float* x  = nullptr;
    const float* Wx = nullptr;
    const float* Wh = nullptr;
    const float* bv = nullptr;
    for (int i = 0; i < n_in; i++) {
        int s = in_sizes[i];
        if (s == BB * TT * DD)      x  = (const float*)d_in[i];
        else if (s == DD * HH)      Wx = (const float*)d_in[i];
        else if (s == HH * HH)      Wh = (const float*)d_in[i];
        else if (s == HH)           bv = (const float*)d_in[i];
    }
    float* out = (float*)d_out;

    static int configured = 0;
    if (!configured) {
        cudaFuncSetAttribute(rnn_persist,
                             cudaFuncAttributeMaxDynamicSharedMemorySize,
                             SMEM_BYTES);
        configured = 1;
    }

    dim3 g1((BB * TT) / 64, HH / 64);
    xp_gemm<<<g1, 256>>>(x, Wx, bv, out);

    rnn_persist<<<128, 512, SMEM_BYTES>>>(out, Wh);
}

// round 12
// speedup vs baseline: 1.2424x; 1.2424x over previous
#include <cuda_runtime.h>
#include <cuda_bf16.h>
#include <cstddef>

// x[64,512,128] @ Wx[128,1024] + b -> XP (in d_out); then
// h_t = tanh(xp_t + h_{t-1} @ Wh[1024,1024]); out[b,t,:] = h_t.
#define BB 64
#define TT 512
#define DD 128
#define HH 1024

typedef unsigned long long ull;

__device__ __forceinline__ ull pk2(float lo, float hi) {
    ull r; asm("mov.b64 %0, {%1, %2};" : "=l"(r) : "f"(lo), "f"(hi)); return r;
}
__device__ __forceinline__ float2 upk2(ull v) {
    float lo, hi; asm("mov.b64 {%0, %1}, %2;" : "=f"(lo), "=f"(hi) : "l"(v));
    return make_float2(lo, hi);
}
__device__ __forceinline__ ull ffma2(ull a, ull b, ull c) {
    ull d; asm("fma.rn.f32x2 %0, %1, %2, %3;" : "=l"(d) : "l"(a), "l"(b), "l"(c));
    return d;
}
__device__ __forceinline__ int ld_acq(const int* p) {
    int v; asm volatile("ld.acquire.gpu.global.s32 %0, [%1];" : "=r"(v) : "l"(p));
    return v;
}
__device__ __forceinline__ void red_rel_add1(int* p) {
    asm volatile("red.release.gpu.global.add.s32 [%0], 1;" :: "l"(p) : "memory");
}
// fast tanh: exp-based, ~1e-6 rel err; clamp avoids inf/inf.
__device__ __forceinline__ float fast_tanh(float x) {
    x = fminf(fmaxf(x, -15.f), 15.f);
    float e = __expf(x + x);
    return __fdividef(e - 1.f, e + 1.f);
}

// ---------- global scratch ----------
__device__ float g_h[2][BB][HH];         // h double buffer, row-major [b][k]
__device__ int   g_flags[4][TT][8];      // (group, step, k-chunk) warp arrivals

// =====================================================================
// Kernel 1: XP = x @ Wx + b  -> d_out   (M=32768, K=128, N=1024)
// Block (0,0) also resets the step flags.
// =====================================================================
__global__ __launch_bounds__(256) void xp_gemm(
    const float* __restrict__ x, const float* __restrict__ Wx,
    const float* __restrict__ bias, float* __restrict__ out)
{
    __shared__ float xs[64 * 68];
    __shared__ float ws[64 * 64];

    const int tid = threadIdx.x;
    if (blockIdx.x == 0 && blockIdx.y == 0) {
        int* f = &g_flags[0][0][0];
        #pragma unroll
        for (int i = tid; i < 4 * TT * 8; i += 256) f[i] = 0;
    }

    const int m0 = blockIdx.x * 64;
    const int n0 = blockIdx.y * 64;
    const int ty = tid >> 4;
    const int tx = tid & 15;

    ull acc01[4] = {0ull, 0ull, 0ull, 0ull};
    ull acc23[4] = {0ull, 0ull, 0ull, 0ull};

    for (int k0 = 0; k0 < DD; k0 += 64) {
        __syncthreads();
        #pragma unroll
        for (int i = tid; i < 1024; i += 256) {
            int r = i >> 4, q = i & 15;
            ((float4*)xs)[r * 17 + q] =
                *(const float4*)&x[(size_t)(m0 + r) * DD + k0 + 4 * q];
        }
        #pragma unroll
        for (int i = tid; i < 1024; i += 256) {
            int r = i >> 4, q = i & 15;
            ((float4*)ws)[i] =
                *(const float4*)&Wx[(size_t)(k0 + r) * HH + n0 + 4 * q];
        }
        __syncthreads();

        #pragma unroll 8
        for (int kk = 0; kk < 64; kk++) {
            ulonglong2 wv = *(const ulonglong2*)&ws[kk * 64 + 4 * tx];
            #pragma unroll
            for (int i = 0; i < 4; i++) {
                float a = xs[(4 * ty + i) * 68 + kk];
                ull aa = pk2(a, a);
                acc01[i] = ffma2(aa, wv.x, acc01[i]);
                acc23[i] = ffma2(aa, wv.y, acc23[i]);
            }
        }
    }

    float4 bv = *(const float4*)&bias[n0 + 4 * tx];
    #pragma unroll
    for (int i = 0; i < 4; i++) {
        float2 p0 = upk2(acc01[i]);
        float2 p1 = upk2(acc23[i]);
        float4 r;
        r.x = p0.x + bv.x; r.y = p0.y + bv.y;
        r.z = p1.x + bv.z; r.w = p1.y + bv.w;
        *(float4*)&out[(size_t)(m0 + 4 * ty + i) * HH + n0 + 4 * tx] = r;
    }
}

// =====================================================================
// Kernel 2: persistent recurrence, TWO independent chains per SM, with
// R5's proven staging/compute mechanics per half.
// 128 CTAs x 512 threads. CTA cid: col slice j = cid&63 (16 cols, Wh
// slice SHARED); half 0 (warps 0-7): group cid>>6, half 1 (warps 8-15):
// group cid>>6 + 2. Halves never sync with each other.
// Per half: warp ks stages+consumes k-chunk ks (128 k x 16 b).
// h layout: row k4 at float4-offset hoff(k4)=(65*k4)>>2 (stride
// 16,16,16,17 repeating; bank-spread stores since 65 is odd);
// batch b at slot perm(b)=(b&3)*4+(b>>2). Staging lanes are k4-major
// (consecutive lanes -> consecutive float4: fully coalesced LDG).
// Compute: lane (cq=lane&7, bq=lane>>3) reads slots bq+4i -> batch
// 4*bq+i (R5's relabeling), cols 2cq/2cq+1; zero per-iter swizzle math
// (hoff(32ks)=520*ks exact; +65 per 4-k4 block).
// red[half][parity][8][16][16] floats; ONE bar.sync(half+1,256)/step;
// parity covers the <=1-step run-ahead the barrier permits.
// Flags target 64 = 8 producer slices x 8 epi warps.
// =====================================================================
#define WB_F4   4096                      /* Wh [256 k4][16 slots] = 64KB */
#define HB_F4   4160                      /* per half: 256 rows, 16.25 avg */
#define RED_ROW 16
#define RED_PAR (8 * 16 * RED_ROW)        /* 2048 floats */
#define SMEM_BYTES (WB_F4*16 + 2*HB_F4*16 + 4*RED_PAR*4)  /* 231,424 B */

__global__ __launch_bounds__(512, 1) void rnn_persist(
    float* __restrict__ out, const float* __restrict__ Wh)
{
    extern __shared__ float4 sm4[];
    float4* wb4  = sm4;                        // [256][16]
    float4* hbb  = sm4 + WB_F4;                // [2][HB_F4]
    float*  redb = (float*)(sm4 + WB_F4 + 2 * HB_F4); // [2][2][RED_PAR]

    const int tid  = threadIdx.x;
    const int half = tid >> 8;
    const int tid2 = tid & 255;
    const int j    = blockIdx.x & 63;
    const int g    = (blockIdx.x >> 6) + 2 * half;
    const int B0   = 16 * g;
    const int C0   = 16 * j;
    const int jc   = j >> 3;                   // chunk this slice feeds

    // one-time: Wh slice [1024 k][16 c] K-transposed into float4 blocks;
    // col c at slot (c&1)*8 + (c>>1)  (slot s<8 = col 2s; s>=8 = col 2(s-8)+1)
    for (int idx = tid; idx < WB_F4; idx += 512) {
        int k4 = idx >> 4, c = idx & 15;
        const float* p = &Wh[(size_t)(4 * k4) * HH + C0 + c];
        float4 v;
        v.x = p[0]; v.y = p[HH]; v.z = p[2 * HH]; v.w = p[3 * HH];
        wb4[k4 * 16 + ((c & 1) * 8 + (c >> 1))] = v;
    }
    __syncthreads();   // only CTA-wide sync; halves independent after this

    const int ks   = tid2 >> 5;     // local warp 0..7 = its k-chunk
    const int lane = tid & 31;
    const int cq   = lane & 7;      // cols 2cq, 2cq+1
    const int bq   = lane >> 3;     // batch group: batches 4bq+i

    // staging: lane = k4-major (coalesced LDG), loop over batches
    const int k4r  = 32 * ks + lane;
    const int hoffr = (65 * k4r) >> 2;

    const int eb = tid2 >> 4;       // epilogue batch 0..15
    const int ec = tid2 & 15;       // epilogue col 0..15

    float4* hb   = hbb + half * HB_F4;
    float*  redh = redb + half * (2 * RED_PAR);

    for (int t = 0; t < TT; t++) {
        const int p = t & 1;
        float* red = redh + p * RED_PAR;

        // prefetch xp (this thread's own output element)
        size_t ob = ((size_t)(B0 + eb) * TT + t) * HH + C0 + ec;
        float xp = __ldcg(&out[ob]);

        if (t > 0) {
            // wait for this chunk's 8 producer slices (64 warp-arrivals)
            const int* fl = &g_flags[g][t - 1][ks];
            while (ld_acq(fl) < 64) { }

            // stage this warp's 128-k chunk of h_{t-1}: coalesced LDGs,
            // perm-slot stores at odd-ish stride (bank-spread)
            {
                const float4* src = (const float4*)&g_h[p ^ 1][B0][0]; // [16][256]
                #pragma unroll
                for (int b = 0; b < 16; b++) {
                    float4 v = __ldcg(src + b * 256 + k4r);
                    hb[hoffr + ((b & 3) * 4 + (b >> 2))] = v;
                }
            }
            __syncwarp();

            // compute 32 k4 (8 blocks of 4, row offsets 0/16/32/48, +65/blk)
            const float4* hbase = hb + 520 * ks + bq;
            const float4* wbase = wb4 + 512 * ks + cq;
            ull a[4][2];
            #pragma unroll
            for (int i = 0; i < 4; i++) { a[i][0] = 0ull; a[i][1] = 0ull; }

            #pragma unroll 2
            for (int m4 = 0; m4 < 8; m4++) {
                const float4* hp = hbase + m4 * 65;
                const float4* wp = wbase + m4 * 64;
                #pragma unroll
                for (int s = 0; s < 4; s++) {
                    const int ho = (s == 0) ? 0 : (s == 1) ? 16 : (s == 2) ? 32 : 48;
                    ulonglong2 w0 = *(const ulonglong2*)(wp + s * 16);
                    ulonglong2 w1 = *(const ulonglong2*)(wp + s * 16 + 8);
                    ulonglong2 h0 = *(const ulonglong2*)(hp + ho + 0);
                    ulonglong2 h1 = *(const ulonglong2*)(hp + ho + 4);
                    ulonglong2 h2 = *(const ulonglong2*)(hp + ho + 8);
                    ulonglong2 h3 = *(const ulonglong2*)(hp + ho + 12);
                    a[0][0] = ffma2(h0.x, w0.x, a[0][0]);
                    a[0][0] = ffma2(h0.y, w0.y, a[0][0]);
                    a[0][1] = ffma2(h0.x, w1.x, a[0][1]);
                    a[0][1] = ffma2(h0.y, w1.y, a[0][1]);
                    a[1][0] = ffma2(h1.x, w0.x, a[1][0]);
                    a[1][0] = ffma2(h1.y, w0.y, a[1][0]);
                    a[1][1] = ffma2(h1.x, w1.x, a[1][1]);
                    a[1][1] = ffma2(h1.y, w1.y, a[1][1]);
                    a[2][0] = ffma2(h2.x, w0.x, a[2][0]);
                    a[2][0] = ffma2(h2.y, w0.y, a[2][0]);
                    a[2][1] = ffma2(h2.x, w1.x, a[2][1]);
                    a[2][1] = ffma2(h2.y, w1.y, a[2][1]);
                    a[3][0] = ffma2(h3.x, w0.x, a[3][0]);
                    a[3][0] = ffma2(h3.y, w0.y, a[3][0]);
                    a[3][1] = ffma2(h3.x, w1.x, a[3][1]);
                    a[3][1] = ffma2(h3.y, w1.y, a[3][1]);
                }
            }

            // horizontal add -> red[ks][batch 4bq+i][col 2cq..2cq+1]
            #pragma unroll
            for (int i = 0; i < 4; i++) {
                float2 v0 = upk2(a[i][0]);
                float2 v1 = upk2(a[i][1]);
                *(float2*)&red[(ks * 16 + 4 * bq + i) * RED_ROW + 2 * cq] =
                    make_float2(v0.x + v0.y, v1.x + v1.y);
            }
        }
        // join this half's 8 warps (drains STS)
        asm volatile("bar.sync %0, 256;" :: "r"(half + 1) : "memory");

        // epilogue: reduce 8 k-chunks, add xp, tanh, publish
        float s = xp;
        if (t > 0) {
            #pragma unroll
            for (int q = 0; q < 8; q++)
                s += red[(q * 16 + eb) * RED_ROW + ec];
        }
        float r = fast_tanh(s);
        g_h[p][B0 + eb][C0 + ec] = r;
        __syncwarp();
        if (lane == 0) red_rel_add1(&g_flags[g][t][jc]);
        out[ob] = r;     // off critical path
    }
}

// =====================================================================
// Launch
// =====================================================================
extern "C" void kernel_launch(void* const* d_in, const int* in_sizes, int n_in,
                              void* d_out, int out_size)
{
    const float* x  = nullptr;
    const float* Wx = nullptr;
    const float* Wh = nullptr;
    const float* bv = nullptr;
    for (int i = 0; i < n_in; i++) {
        int s = in_sizes[i];
        if (s == BB * TT * DD)      x  = (const float*)d_in[i];
        else if (s == DD * HH)      Wx = (const float*)d_in[i];
        else if (s == HH * HH)      Wh = (const float*)d_in[i];
        else if (s == HH)           bv = (const float*)d_in[i];
    }
    float* out = (float*)d_out;

    static int configured = 0;
    if (!configured) {
        cudaFuncSetAttribute(rnn_persist,
                             cudaFuncAttributeMaxDynamicSharedMemorySize,
                             SMEM_BYTES);
        configured = 1;
    }

    dim3 g1((BB * TT) / 64, HH / 64);
    xp_gemm<<<g1, 256>>>(x, Wx, bv, out);

    rnn_persist<<<128, 512, SMEM_BYTES>>>(out, Wh);
}

// round 15
// speedup vs baseline: 2.5016x; 2.0136x over previous
#include <cuda_runtime.h>
#include <cuda_bf16.h>
#include <cstddef>
#include <cstdint>

// x[64,512,128] @ Wx[128,1024] + b -> XP (in d_out); then
// h_t = tanh(xp_t + h_{t-1} @ Wh[1024,1024]); out[b,t,:] = h_t.
#define BB 64
#define TT 512
#define DD 128
#define HH 1024

typedef unsigned long long ull;

__device__ __forceinline__ ull pk2(float lo, float hi) {
    ull r; asm("mov.b64 %0, {%1, %2};" : "=l"(r) : "f"(lo), "f"(hi)); return r;
}
__device__ __forceinline__ float2 upk2(ull v) {
    float lo, hi; asm("mov.b64 {%0, %1}, %2;" : "=f"(lo), "=f"(hi) : "l"(v));
    return make_float2(lo, hi);
}
__device__ __forceinline__ ull ffma2(ull a, ull b, ull c) {
    ull d; asm("fma.rn.f32x2 %0, %1, %2, %3;" : "=l"(d) : "l"(a), "l"(b), "l"(c));
    return d;
}
__device__ __forceinline__ int ld_acq(const int* p) {
    int v; asm volatile("ld.acquire.gpu.global.s32 %0, [%1];" : "=r"(v) : "l"(p));
    return v;
}
__device__ __forceinline__ void red_rel_add1(int* p) {
    asm volatile("red.release.gpu.global.add.s32 [%0], 1;" :: "l"(p) : "memory");
}
__device__ __forceinline__ uint32_t smem_u32(const void* p) {
    uint32_t a;
    asm("{ .reg .u64 t; cvta.to.shared.u64 t, %1; cvt.u32.u64 %0, t; }"
        : "=r"(a) : "l"(p));
    return a;
}
__device__ __forceinline__ float fast_tanh(float x) {
    x = fminf(fmaxf(x, -15.f), 15.f);
    float e = __expf(x + x);
    return __fdividef(e - 1.f, e + 1.f);
}
__device__ __forceinline__ uint32_t pack_bf2(float a, float b) {
    __nv_bfloat162 v = __floats2bfloat162_rn(a, b);
    return *(uint32_t*)&v;
}

// warp-level MMA (sm_80 PTX; no arch-suffix features)
__device__ __forceinline__ void mma16816(
    float& d0, float& d1, float& d2, float& d3,
    uint32_t a0, uint32_t a1, uint32_t a2, uint32_t a3,
    uint32_t b0, uint32_t b1)
{
    asm volatile(
        "mma.sync.aligned.m16n8k16.row.col.f32.bf16.bf16.f32 "
        "{%0,%1,%2,%3}, {%4,%5,%6,%7}, {%8,%9}, {%0,%1,%2,%3};"
        : "+f"(d0), "+f"(d1), "+f"(d2), "+f"(d3)
        : "r"(a0), "r"(a1), "r"(a2), "r"(a3), "r"(b0), "r"(b1));
}
__device__ __forceinline__ void ldsm4(uint32_t& r0, uint32_t& r1,
                                      uint32_t& r2, uint32_t& r3, uint32_t a) {
    asm volatile("ldmatrix.sync.aligned.m8n8.x4.shared.b16 {%0,%1,%2,%3}, [%4];"
                 : "=r"(r0), "=r"(r1), "=r"(r2), "=r"(r3) : "r"(a));
}
__device__ __forceinline__ void ldsm2(uint32_t& r0, uint32_t& r1, uint32_t a) {
    asm volatile("ldmatrix.sync.aligned.m8n8.x2.shared.b16 {%0,%1}, [%2];"
                 : "=r"(r0), "=r"(r1) : "r"(a));
}

// ---------- global scratch ----------
__device__ __nv_bfloat16 g_hHI[2][BB][HH];   // h hi plane [b][k]
__device__ __nv_bfloat16 g_hLO[2][BB][HH];   // h lo plane
__device__ int g_flags[4][TT][8];            // (group, step, chunk) arrivals

// =====================================================================
// Kernel 1: XP = x @ Wx + b  -> d_out  (also resets flags)
// =====================================================================
__global__ __launch_bounds__(256) void xp_gemm(
    const float* __restrict__ x, const float* __restrict__ Wx,
    const float* __restrict__ bias, float* __restrict__ out)
{
    __shared__ float xs[64 * 68];
    __shared__ float ws[64 * 64];

    const int tid = threadIdx.x;
    if (blockIdx.x == 0 && blockIdx.y == 0) {
        int* f = &g_flags[0][0][0];
        for (int i = tid; i < 4 * TT * 8; i += 256) f[i] = 0;
    }

    const int m0 = blockIdx.x * 64;
    const int n0 = blockIdx.y * 64;
    const int ty = tid >> 4;
    const int tx = tid & 15;

    ull acc01[4] = {0ull, 0ull, 0ull, 0ull};
    ull acc23[4] = {0ull, 0ull, 0ull, 0ull};

    for (int k0 = 0; k0 < DD; k0 += 64) {
        __syncthreads();
        #pragma unroll
        for (int i = tid; i < 1024; i += 256) {
            int r = i >> 4, q = i & 15;
            ((float4*)xs)[r * 17 + q] =
                *(const float4*)&x[(size_t)(m0 + r) * DD + k0 + 4 * q];
        }
        #pragma unroll
        for (int i = tid; i < 1024; i += 256) {
            int r = i >> 4, q = i & 15;
            ((float4*)ws)[i] =
                *(const float4*)&Wx[(size_t)(k0 + r) * HH + n0 + 4 * q];
        }
        __syncthreads();

        #pragma unroll 8
        for (int kk = 0; kk < 64; kk++) {
            ulonglong2 wv = *(const ulonglong2*)&ws[kk * 64 + 4 * tx];
            #pragma unroll
            for (int i = 0; i < 4; i++) {
                float a = xs[(4 * ty + i) * 68 + kk];
                ull aa = pk2(a, a);
                acc01[i] = ffma2(aa, wv.x, acc01[i]);
                acc23[i] = ffma2(aa, wv.y, acc23[i]);
            }
        }
    }

    float4 bv = *(const float4*)&bias[n0 + 4 * tx];
    #pragma unroll
    for (int i = 0; i < 4; i++) {
        float2 p0 = upk2(acc01[i]);
        float2 p1 = upk2(acc23[i]);
        float4 r;
        r.x = p0.x + bv.x; r.y = p0.y + bv.y;
        r.z = p1.x + bv.z; r.w = p1.y + bv.w;
        *(float4*)&out[(size_t)(m0 + 4 * ty + i) * HH + n0 + 4 * tx] = r;
    }
}

// =====================================================================
// Kernel 2: persistent recurrence via mma.sync (HMMA tensor pipe).
// 128 CTAs x 256 thr (8 warps). CTA (g=bid>>5, j=bid&31): batches
// [16g,16g+16), cols [32j,32j+32); produces k-chunk j>>2.
// Warp ks stages+consumes k-chunk ks (128 k): D16x32 partial =
// A(h hi/lo bf16, [16][128]) x B(WhT hi/lo, [32 n][128 k]) via
// m16n8k16 bf16 MMAs, 3 passes (hi*hi + hi*lo + lo*hi) = fp32-faithful.
// SMEM (bf16 rows padded to 1040 elems = 2080B, bank-spread):
//   Bhi/Blo [32][1040], Ahi/Alo [16][1040], red[8][16][34] float.
// Sync: R5 scheme — per-chunk flags (target 32 = 4 CTAs x 8 warps),
// two bar.sync per step.
// =====================================================================
#define LROW 1040
#define SM_BHI 0
#define SM_BLO (SM_BHI + 32 * LROW * 2)     /* 66560 */
#define SM_AHI (SM_BLO + 32 * LROW * 2)     /* 133120 */
#define SM_ALO (SM_AHI + 16 * LROW * 2)     /* 166400 */
#define SM_RED (SM_ALO + 16 * LROW * 2)     /* 199680 */
#define RED_ROW 34
#define SMEM_BYTES (SM_RED + 8 * 16 * RED_ROW * 4)   /* 217088 */

__global__ __launch_bounds__(256, 1) void rnn_persist(
    float* __restrict__ out, const float* __restrict__ Wh)
{
    extern __shared__ char smem[];
    const int tid  = threadIdx.x;
    const int g    = blockIdx.x >> 5;
    const int j    = blockIdx.x & 31;
    const int B0   = 16 * g;
    const int C0   = 32 * j;
    const int jc   = j >> 2;

    // one-time: B = WhT slice [32 n][1024 k] hi/lo bf16
    for (int idx = tid; idx < 32 * HH; idx += 256) {
        int n = idx & 31, k = idx >> 5;
        float w = Wh[(size_t)k * HH + C0 + n];
        __nv_bfloat16 hi = __float2bfloat16(w);
        __nv_bfloat16 lo = __float2bfloat16(w - __bfloat162float(hi));
        *(__nv_bfloat16*)(smem + SM_BHI + (n * LROW + k) * 2) = hi;
        *(__nv_bfloat16*)(smem + SM_BLO + (n * LROW + k) * 2) = lo;
    }
    __syncthreads();

    const int ks   = tid >> 5;      // warp = its k-chunk
    const int lane = tid & 31;

    // ldmatrix source addresses (k-chunk base folded in)
    const uint32_t sb = smem_u32(smem);
    const uint32_t aAhi = sb + SM_AHI +
        (uint32_t)(((lane & 15) * LROW + 128 * ks + 8 * (lane >> 4)) * 2);
    const uint32_t aAlo = aAhi + (SM_ALO - SM_AHI);
    const uint32_t aBhi = sb + SM_BHI +
        (uint32_t)(((lane & 7) * LROW + 128 * ks + 8 * ((lane >> 3) & 1)) * 2);
    const uint32_t aBlo = aBhi + (SM_BLO - SM_BHI);

    float* red = (float*)(smem + SM_RED);

    const int eb = tid >> 4;        // epilogue batch 0..15
    const int ec2 = 2 * (tid & 15); // epilogue col pair

    for (int t = 0; t < TT; t++) {
        // prefetch xp
        size_t ob = ((size_t)(B0 + eb) * TT + t) * HH + C0 + ec2;
        float2 xp = __ldcg((const float2*)&out[ob]);

        if (t > 0) {
            const int pp = (t - 1) & 1;
            // wait for this chunk's 4 producer CTAs (32 warp-arrivals)
            const int* fl = &g_flags[g][t - 1][ks];
            while (ld_acq(fl) < 32) { }

            // stage own 128-k chunk of h hi/lo: [16 rows][128 k]
            {
                const __nv_bfloat16* sH = &g_hHI[pp][B0][0];
                const __nv_bfloat16* sL = &g_hLO[pp][B0][0];
                const int q = lane & 15;
                #pragma unroll
                for (int i = 0; i < 8; i++) {
                    int r = 2 * i + (lane >> 4);
                    int so = r * HH + 128 * ks;
                    uint4 vh = __ldcg((const uint4*)(sH + so) + q);
                    uint4 vl = __ldcg((const uint4*)(sL + so) + q);
                    int doff = (r * LROW + 128 * ks + 8 * q) * 2;
                    *(uint4*)(smem + SM_AHI + doff) = vh;
                    *(uint4*)(smem + SM_ALO + doff) = vl;
                }
            }
            __syncwarp();

            // compute: 8 ktiles x 4 ntiles x 3 MMAs
            float d[4][4];
            #pragma unroll
            for (int nt = 0; nt < 4; nt++)
                #pragma unroll
                for (int i = 0; i < 4; i++) d[nt][i] = 0.f;

            #pragma unroll 2
            for (int m = 0; m < 8; m++) {
                uint32_t ah0, ah1, ah2, ah3, al0, al1, al2, al3;
                ldsm4(ah0, ah1, ah2, ah3, aAhi + m * 32);
                ldsm4(al0, al1, al2, al3, aAlo + m * 32);
                #pragma unroll
                for (int nt = 0; nt < 4; nt++) {
                    uint32_t bh0, bh1, bl0, bl1;
                    uint32_t bo = (uint32_t)(nt * (8 * LROW * 2) + m * 32);
                    ldsm2(bh0, bh1, aBhi + bo);
                    ldsm2(bl0, bl1, aBlo + bo);
                    mma16816(d[nt][0], d[nt][1], d[nt][2], d[nt][3],
                             ah0, ah1, ah2, ah3, bh0, bh1);
                    mma16816(d[nt][0], d[nt][1], d[nt][2], d[nt][3],
                             ah0, ah1, ah2, ah3, bl0, bl1);
                    mma16816(d[nt][0], d[nt][1], d[nt][2], d[nt][3],
                             al0, al1, al2, al3, bh0, bh1);
                }
            }

            // write partials: D frag rows lane>>2 / +8, cols 2(lane&3)
            {
                const int r1 = lane >> 2;
                const int cc = 2 * (lane & 3);
                #pragma unroll
                for (int nt = 0; nt < 4; nt++) {
                    int nc = 8 * nt + cc;
                    *(float2*)&red[(ks * 16 + r1) * RED_ROW + nc] =
                        make_float2(d[nt][0], d[nt][1]);
                    *(float2*)&red[(ks * 16 + r1 + 8) * RED_ROW + nc] =
                        make_float2(d[nt][2], d[nt][3]);
                }
            }
        }
        __syncthreads();   // join: all partials in red

        // epilogue: reduce 8 chunks, add xp, tanh, publish
        float s0 = xp.x, s1 = xp.y;
        if (t > 0) {
            #pragma unroll
            for (int q = 0; q < 8; q++) {
                float2 rv = *(const float2*)&red[(q * 16 + eb) * RED_ROW + ec2];
                s0 += rv.x; s1 += rv.y;
            }
        }
        float r0 = fast_tanh(s0), r1 = fast_tanh(s1);
        const int hp = t & 1;
        {
            __nv_bfloat16 h0 = __float2bfloat16(r0);
            __nv_bfloat16 h1 = __float2bfloat16(r1);
            float l0 = r0 - __bfloat162float(h0);
            float l1 = r1 - __bfloat162float(h1);
            *(uint32_t*)&g_hHI[hp][B0 + eb][C0 + ec2] = pack_bf2(r0, r1);
            *(uint32_t*)&g_hLO[hp][B0 + eb][C0 + ec2] = pack_bf2(l0, l1);
        }
        __syncwarp();
        if (lane == 0) red_rel_add1(&g_flags[g][t][jc]);
        *(float2*)&out[ob] = make_float2(r0, r1);   // off critical path

        __syncthreads();   // red reuse hazard fence
    }
}

// =====================================================================
// Launch
// =====================================================================
extern "C" void kernel_launch(void* const* d_in, const int* in_sizes, int n_in,
                              void* d_out, int out_size)
{
    const float* x  = nullptr;
    const float* Wx = nullptr;
    const float* Wh = nullptr;
    const float* bv = nullptr;
    for (int i = 0; i < n_in; i++) {
        int s = in_sizes[i];
        if (s == BB * TT * DD)      x  = (const float*)d_in[i];
        else if (s == DD * HH)      Wx = (const float*)d_in[i];
        else if (s == HH * HH)      Wh = (const float*)d_in[i];
        else if (s == HH)           bv = (const float*)d_in[i];
    }
    float* out = (float*)d_out;

    static int configured = 0;
    if (!configured) {
        cudaFuncSetAttribute(rnn_persist,
                             cudaFuncAttributeMaxDynamicSharedMemorySize,
                             SMEM_BYTES);
        configured = 1;
    }

    dim3 g1((BB * TT) / 64, HH / 64);
    xp_gemm<<<g1, 256>>>(x, Wx, bv, out);

    rnn_persist<<<128, 256, SMEM_BYTES>>>(out, Wh);
}